// round 4
// baseline (speedup 1.0000x reference)
#include <cuda_runtime.h>
#include <math.h>
#include <stdint.h>

#define NB 256
#define NCH 256
#define ROI 7

static __device__ __forceinline__ float neginf() {
    return __int_as_float(0xff800000);
}

// RN(1/7), emulating XLA's divide-by-constant -> multiply-by-reciprocal rewrite
#define R7 (1.0f / 7.0f)

__global__ __launch_bounds__(256) void roi_pool_kernel(
    const float* __restrict__ ft0, const float* __restrict__ ft1,
    const float* __restrict__ ft2, const float* __restrict__ ft3,
    const float* __restrict__ rois, const int* __restrict__ roi_idx,
    float* __restrict__ out)
{
    const int gw   = (blockIdx.x * blockDim.x + threadIdx.x) >> 5;  // global warp id
    const int lane = threadIdx.x & 31;
    if (gw >= NB * NCH) return;
    const int roi = gw >> 8;       // / NCH
    const int c   = gw & (NCH - 1);

    // ROI box (broadcast loads, L1-resident)
    const float y1 = rois[roi * 4 + 0];
    const float x1 = rois[roi * 4 + 1];
    const float y2 = rois[roi * 4 + 2];
    const float x2 = rois[roi * 4 + 3];
    const int img  = roi_idx[roi];

    // Level: clip(floor(4 + log2(b/224)), 2, 5) - 2  ==  thresholds at 112/224/448
    const float bsz = __fsqrt_rn(__fmul_rn(__fadd_rn(y2, -y1), __fadd_rn(x2, -x1)));
    const int l = (bsz >= 112.0f ? 1 : 0) + (bsz >= 224.0f ? 1 : 0) +
                  (bsz >= 448.0f ? 1 : 0);   // 0..3

    int H;
    const float* base;
    float scale;
    if (l == 0)      { H = 200; base = ft0; scale = 0.25f;    }
    else if (l == 1) { H = 100; base = ft1; scale = 0.125f;   }
    else if (l == 2) { H = 50;  base = ft2; scale = 0.0625f;  }
    else             { H = 25;  base = ft3; scale = 0.03125f; }
    const int W = H;
    base += ((size_t)img * NCH + (size_t)c) * (size_t)(H * W);

    // round-half-up endpoints (exact f32 RN ops)
    const int sh = (int)floorf(__fadd_rn(__fmul_rn(y1, scale), 0.5f));
    const int sw = (int)floorf(__fadd_rn(__fmul_rn(x1, scale), 0.5f));
    const int eh = (int)floorf(__fadd_rn(__fmul_rn(y2, scale), 0.5f));
    const int ew = (int)floorf(__fadd_rn(__fmul_rn(x2, scale), 0.5f));
    const float roi_h = (float)max(eh - sh + 1, 1);
    const float roi_w = (float)max(ew - sw + 1, 1);
    // KEY CHANGE: reciprocal multiply (XLA emulation), NOT true division
    const float bh = __fmul_rn(roi_h, R7);
    const float bw = __fmul_rn(roi_w, R7);

    // Per-lane pw-bin bounds (lanes 0..6 are the 7 output columns)
    const int pw  = (lane < 7) ? lane : 0;
    const int ws_ = min(max((int)floorf(__fmul_rn((float)pw, bw)) + sw, 0), W);
    const int we_ = min(max((int)ceilf(__fmul_rn((float)pw + 1.0f, bw)) + sw, 0), W);

    // Window column base + max extent (width <= 31 < 32 incl. the +1-ulp ceil case)
    const int wbase   = min(max(sw, 0), W);
    const int wendmax = min(max((int)ceilf(__fmul_rn(7.0f, bw)) + sw, 0), W);
    const int col     = wbase + lane;
    const bool cv     = (col < wendmax);

    const int src0 = (ws_ - wbase) & 31;

    #pragma unroll
    for (int ph = 0; ph < ROI; ++ph) {
        const int hs = min(max((int)floorf(__fmul_rn((float)ph, bh)) + sh, 0), H);
        const int he = min(max((int)ceilf(__fmul_rn((float)ph + 1.0f, bh)) + sh, 0), H);

        // Column-max over this h-bin's rows (coalesced 128B row loads)
        float colmax = neginf();
        const float* rowp = base + (size_t)hs * W + col;
        for (int h = hs; h < he; ++h) {
            if (cv) colmax = fmaxf(colmax, __ldg(rowp));
            rowp += W;
        }

        // Each lane<7 reduces its pw-bin lane range via per-lane-indexed shuffles
        float m = neginf();
        #pragma unroll
        for (int k = 0; k < 8; ++k) {
            const float v = __shfl_sync(0xffffffffu, colmax, (src0 + k) & 31);
            if (ws_ + k < we_) m = fmaxf(m, v);
        }

        if (lane < 7) {
            const bool empty = (he <= hs) || (we_ <= ws_);
            out[(((size_t)roi * NCH + c) * ROI + ph) * ROI + lane] = empty ? 0.0f : m;
        }
    }
}

extern "C" void kernel_launch(void* const* d_in, const int* in_sizes, int n_in,
                              void* d_out, int out_size) {
    // Bind inputs by unique element count (robust to metadata ordering)
    const float* ft0 = 0; const float* ft1 = 0; const float* ft2 = 0;
    const float* ft3 = 0; const float* rois = 0; const int* roi_idx = 0;
    for (int i = 0; i < n_in; ++i) {
        switch (in_sizes[i]) {
            case 2 * 256 * 200 * 200: ft0 = (const float*)d_in[i]; break;
            case 2 * 256 * 100 * 100: ft1 = (const float*)d_in[i]; break;
            case 2 * 256 * 50 * 50:   ft2 = (const float*)d_in[i]; break;
            case 2 * 256 * 25 * 25:   ft3 = (const float*)d_in[i]; break;
            case 256 * 4:             rois = (const float*)d_in[i]; break;
            case 256:                 roi_idx = (const int*)d_in[i]; break;
        }
    }
    float* out = (float*)d_out;

    const int total_warps = NB * NCH;          // 65536
    const int threads = 256;                   // 8 warps/block
    const int blocks = (total_warps * 32 + threads - 1) / threads;  // 8192
    roi_pool_kernel<<<blocks, threads>>>(ft0, ft1, ft2, ft3, rois, roi_idx, out);
}

// round 5
// speedup vs baseline: 1.3333x; 1.3333x over previous
#include <cuda_runtime.h>
#include <math.h>
#include <stdint.h>

#define NB 256
#define NCH 256
#define ROI 7

static __device__ __forceinline__ float neginf() {
    return __int_as_float(0xff800000);
}

// RN(1/7): XLA rewrites divide-by-constant into multiply-by-reciprocal.
// This MUST stay a multiply (bit-exactness depends on it).
#define R7 (1.0f / 7.0f)

__global__ __launch_bounds__(256) void roi_pool_fast(
    const float* __restrict__ ft0, const float* __restrict__ ft1,
    const float* __restrict__ ft2, const float* __restrict__ ft3,
    const float* __restrict__ rois, const int* __restrict__ roi_idx,
    float* __restrict__ out)
{
    __shared__ int s_hs[8], s_he[8], s_ws[8], s_we[8];
    __shared__ int s_hdr[4];   // W, level, img, wbase

    const int roi  = blockIdx.x >> 5;          // 32 blocks per ROI
    const int cg   = (blockIdx.x & 31) << 3;   // block's base channel
    const int wid  = threadIdx.x >> 5;
    const int lane = threadIdx.x & 31;
    const int tid  = threadIdx.x;

    // ---- per-ROI scalar math, once per block (threads 0..7) ----
    if (tid < 8) {
        const float y1 = rois[roi * 4 + 0];
        const float x1 = rois[roi * 4 + 1];
        const float y2 = rois[roi * 4 + 2];
        const float x2 = rois[roi * 4 + 3];

        // level = clip(floor(4+log2(bsz/224)),2,5)-2 == thresholds 112/224/448
        const float bsz = __fsqrt_rn(__fmul_rn(__fadd_rn(y2, -y1), __fadd_rn(x2, -x1)));
        const int l = (bsz >= 112.0f ? 1 : 0) + (bsz >= 224.0f ? 1 : 0) +
                      (bsz >= 448.0f ? 1 : 0);
        const int H = 200 >> l;                         // 200,100,50,25
        const float scale = 0.25f / (float)(1 << l);    // exact powers of two

        const int sh = (int)floorf(__fadd_rn(__fmul_rn(y1, scale), 0.5f));
        const int sw = (int)floorf(__fadd_rn(__fmul_rn(x1, scale), 0.5f));
        const int eh = (int)floorf(__fadd_rn(__fmul_rn(y2, scale), 0.5f));
        const int ew = (int)floorf(__fadd_rn(__fmul_rn(x2, scale), 0.5f));
        const float bh = __fmul_rn((float)max(eh - sh + 1, 1), R7);
        const float bw = __fmul_rn((float)max(ew - sw + 1, 1), R7);

        const int p = tid;                // p=7 writes unused slot 7 (harmless)
        const float pf = (float)p;
        s_hs[p] = min(max((int)floorf(__fmul_rn(pf, bh)) + sh, 0), H);
        s_he[p] = min(max((int)ceilf(__fmul_rn(__fadd_rn(pf, 1.0f), bh)) + sh, 0), H);
        s_ws[p] = min(max((int)floorf(__fmul_rn(pf, bw)) + sw, 0), H);
        s_we[p] = min(max((int)ceilf(__fmul_rn(__fadd_rn(pf, 1.0f), bw)) + sw, 0), H);
        if (tid == 0) {
            s_hdr[0] = H;
            s_hdr[1] = l;
            s_hdr[2] = roi_idx[roi];
            s_hdr[3] = min(max(sw, 0), H);   // wbase
        }
    }
    __syncthreads();

    const int W     = s_hdr[0];
    const int lvl   = s_hdr[1];
    const int img   = s_hdr[2];
    const int wbase = s_hdr[3];
    const int c     = cg + wid;

    const float* ftp = (lvl == 0) ? ft0 : (lvl == 1) ? ft1 : (lvl == 2) ? ft2 : ft3;
    // lane column, clamped in-bounds (garbage columns never consumed)
    const int colc = min(wbase + lane, W - 1);
    const float* base = ftp + (size_t)(img * NCH + c) * (size_t)(W * W) + colc;

    // lane-resident pw-bin data (lanes 0..6 are output columns)
    const int pw   = (lane < 7) ? lane : 0;
    const int wsL  = s_ws[pw];
    const int cnt  = s_we[pw] - wsL;       // segment length, <= 6
    const int src0 = wsL - wbase;          // first source lane, <= 24

    float* op = out + ((size_t)roi * NCH + c) * (ROI * ROI) + pw;

    #pragma unroll
    for (int ph = 0; ph < ROI; ++ph) {
        const int hs  = s_hs[ph];
        const int he  = s_he[ph];
        const int nr1 = max(he - hs, 1) - 1;           // 0..5
        const float* a = base + (size_t)min(hs, W - 1) * W;

        // 6 independent clamped loads (duplicates idempotent under max)
        const float v0 = __ldg(a);
        const float v1 = __ldg(a + min(1, nr1) * W);
        const float v2 = __ldg(a + min(2, nr1) * W);
        const float v3 = __ldg(a + min(3, nr1) * W);
        const float v4 = __ldg(a + min(4, nr1) * W);
        const float v5 = __ldg(a + nr1 * W);
        const float cm = fmaxf(fmaxf(fmaxf(v0, v1), fmaxf(v2, v3)), fmaxf(v4, v5));

        // segment max over [src0, src0+cnt) via 6 shuffles (cnt <= 6 proven)
        float m = __shfl_sync(0xffffffffu, cm, src0);
        #pragma unroll
        for (int k = 1; k < 6; ++k) {
            const float v = __shfl_sync(0xffffffffu, cm, src0 + k);
            if (k < cnt) m = fmaxf(m, v);
        }

        if (lane < 7) {
            const bool empty = (he <= hs) || (cnt <= 0);
            *op = empty ? 0.0f : m;
        }
        op += ROI;
    }
}

extern "C" void kernel_launch(void* const* d_in, const int* in_sizes, int n_in,
                              void* d_out, int out_size) {
    const float* ft0 = 0; const float* ft1 = 0; const float* ft2 = 0;
    const float* ft3 = 0; const float* rois = 0; const int* roi_idx = 0;
    for (int i = 0; i < n_in; ++i) {
        switch (in_sizes[i]) {
            case 2 * 256 * 200 * 200: ft0 = (const float*)d_in[i]; break;
            case 2 * 256 * 100 * 100: ft1 = (const float*)d_in[i]; break;
            case 2 * 256 * 50 * 50:   ft2 = (const float*)d_in[i]; break;
            case 2 * 256 * 25 * 25:   ft3 = (const float*)d_in[i]; break;
            case 256 * 4:             rois = (const float*)d_in[i]; break;
            case 256:                 roi_idx = (const int*)d_in[i]; break;
        }
    }
    float* out = (float*)d_out;

    // block = 8 warps = 8 channels of one ROI; 32 blocks per ROI
    roi_pool_fast<<<NB * 32, 256>>>(ft0, ft1, ft2, ft3, rois, roi_idx, out);
}

// round 6
// speedup vs baseline: 1.7721x; 1.3290x over previous
#include <cuda_runtime.h>
#include <math.h>
#include <stdint.h>

#define NB 256
#define NCH 256
#define ROI 7

static __device__ __forceinline__ float neginf() {
    return __int_as_float(0xff800000);
}

// RN(1/7): XLA rewrites divide-by-constant into multiply-by-reciprocal.
// This MUST stay a multiply (bit-exactness depends on it).
#define R7 (1.0f / 7.0f)

template <int W>
static __device__ __forceinline__ void pool_body(
    const float* __restrict__ ftp, float* __restrict__ out,
    const int2* s_h, const int2* s_w,
    int roi, int c, int img, int wbase, int lane)
{
    const int colc = min(wbase + lane, W - 1);
    const float* base = ftp + (size_t)(img * NCH + c) * (size_t)(W * W) + colc;

    // lane-resident pw-bin data (lanes 0..6 are output columns)
    const int pw   = (lane < 7) ? lane : 0;
    const int2 wb  = s_w[pw];
    const int cnt  = wb.y - wb.x;          // <= 6
    const int src0 = wb.x - wbase;         // >= 0, <= 24

    float* op = out + ((size_t)roi * NCH + c) * (ROI * ROI) + pw;

    #pragma unroll
    for (int ph = 0; ph < ROI; ++ph) {
        const int2 hb   = s_h[ph];
        const int nrows = hb.y - hb.x;                 // warp-uniform, <= 6
        const float* a  = base + hb.x * W;             // W is compile-time

        // warp-uniform predicated loads: skipped LDGs cost no L1 wavefront
        float v0 = neginf(), v1 = neginf(), v2 = neginf();
        float v3 = neginf(), v4 = neginf(), v5 = neginf();
        if (nrows > 0) v0 = __ldg(a);
        if (nrows > 1) v1 = __ldg(a + W);
        if (nrows > 2) v2 = __ldg(a + 2 * W);
        if (nrows > 3) v3 = __ldg(a + 3 * W);
        if (nrows > 4) v4 = __ldg(a + 4 * W);
        if (nrows > 5) v5 = __ldg(a + 5 * W);
        const float cm = fmaxf(fmaxf(fmaxf(v0, v1), fmaxf(v2, v3)), fmaxf(v4, v5));

        // segment max over lanes [src0, src0+cnt) via indexed shuffles
        float m = __shfl_sync(0xffffffffu, cm, src0);
        #pragma unroll
        for (int k = 1; k < 6; ++k) {
            const float v = __shfl_sync(0xffffffffu, cm, src0 + k);
            if (k < cnt) m = fmaxf(m, v);
        }

        if (lane < 7) {
            const bool empty = (nrows <= 0) || (cnt <= 0);
            *op = empty ? 0.0f : m;
        }
        op += ROI;
    }
}

__global__ __launch_bounds__(256, 8) void roi_pool_fast(
    const float* __restrict__ ft0, const float* __restrict__ ft1,
    const float* __restrict__ ft2, const float* __restrict__ ft3,
    const float* __restrict__ rois, const int* __restrict__ roi_idx,
    float* __restrict__ out)
{
    __shared__ int2 s_h[8], s_w[8];
    __shared__ int  s_hdr[4];   // W, level, img, wbase

    const int roi  = blockIdx.x >> 5;          // 32 blocks per ROI
    const int cg   = (blockIdx.x & 31) << 3;   // block's base channel
    const int wid  = threadIdx.x >> 5;
    const int lane = threadIdx.x & 31;
    const int tid  = threadIdx.x;

    // ---- per-ROI scalar math, once per block (threads 0..7) ----
    if (tid < 8) {
        const float y1 = rois[roi * 4 + 0];
        const float x1 = rois[roi * 4 + 1];
        const float y2 = rois[roi * 4 + 2];
        const float x2 = rois[roi * 4 + 3];

        // level = clip(floor(4+log2(bsz/224)),2,5)-2 == thresholds 112/224/448
        const float bsz = __fsqrt_rn(__fmul_rn(__fadd_rn(y2, -y1), __fadd_rn(x2, -x1)));
        const int l = (bsz >= 112.0f ? 1 : 0) + (bsz >= 224.0f ? 1 : 0) +
                      (bsz >= 448.0f ? 1 : 0);
        const int H = 200 >> l;                         // 200,100,50,25
        const float scale = 0.25f / (float)(1 << l);    // exact powers of two

        const int sh = (int)floorf(__fadd_rn(__fmul_rn(y1, scale), 0.5f));
        const int sw = (int)floorf(__fadd_rn(__fmul_rn(x1, scale), 0.5f));
        const int eh = (int)floorf(__fadd_rn(__fmul_rn(y2, scale), 0.5f));
        const int ew = (int)floorf(__fadd_rn(__fmul_rn(x2, scale), 0.5f));
        const float bh = __fmul_rn((float)max(eh - sh + 1, 1), R7);
        const float bw = __fmul_rn((float)max(ew - sw + 1, 1), R7);

        const int p = tid;                // p=7 fills unused slot 7 (harmless)
        const float pf = (float)p;
        int2 hb, wb;
        hb.x = min(max((int)floorf(__fmul_rn(pf, bh)) + sh, 0), H);
        hb.y = min(max((int)ceilf(__fmul_rn(__fadd_rn(pf, 1.0f), bh)) + sh, 0), H);
        wb.x = min(max((int)floorf(__fmul_rn(pf, bw)) + sw, 0), H);
        wb.y = min(max((int)ceilf(__fmul_rn(__fadd_rn(pf, 1.0f), bw)) + sw, 0), H);
        s_h[p] = hb;
        s_w[p] = wb;
        if (tid == 0) {
            s_hdr[0] = H;
            s_hdr[1] = l;
            s_hdr[2] = roi_idx[roi];
            s_hdr[3] = min(max(sw, 0), H);   // wbase
        }
    }
    __syncthreads();

    const int lvl   = s_hdr[1];
    const int img   = s_hdr[2];
    const int wbase = s_hdr[3];
    const int c     = cg + wid;

    // per-block uniform dispatch to the compile-time-W body
    switch (lvl) {
        case 0:  pool_body<200>(ft0, out, s_h, s_w, roi, c, img, wbase, lane); break;
        case 1:  pool_body<100>(ft1, out, s_h, s_w, roi, c, img, wbase, lane); break;
        case 2:  pool_body<50> (ft2, out, s_h, s_w, roi, c, img, wbase, lane); break;
        default: pool_body<25> (ft3, out, s_h, s_w, roi, c, img, wbase, lane); break;
    }
}

extern "C" void kernel_launch(void* const* d_in, const int* in_sizes, int n_in,
                              void* d_out, int out_size) {
    const float* ft0 = 0; const float* ft1 = 0; const float* ft2 = 0;
    const float* ft3 = 0; const float* rois = 0; const int* roi_idx = 0;
    for (int i = 0; i < n_in; ++i) {
        switch (in_sizes[i]) {
            case 2 * 256 * 200 * 200: ft0 = (const float*)d_in[i]; break;
            case 2 * 256 * 100 * 100: ft1 = (const float*)d_in[i]; break;
            case 2 * 256 * 50 * 50:   ft2 = (const float*)d_in[i]; break;
            case 2 * 256 * 25 * 25:   ft3 = (const float*)d_in[i]; break;
            case 256 * 4:             rois = (const float*)d_in[i]; break;
            case 256:                 roi_idx = (const int*)d_in[i]; break;
        }
    }
    float* out = (float*)d_out;

    // block = 8 warps = 8 channels of one ROI; 32 blocks per ROI
    roi_pool_fast<<<NB * 32, 256>>>(ft0, ft1, ft2, ft3, rois, roi_idx, out);
}